// round 1
// baseline (speedup 1.0000x reference)
#include <cuda_runtime.h>

#define Gn 1024
#define Tn 200
#define Sn 16
#define Mn 4

// One CTA per group g. 256 threads: thread (i,j) owns cov element [i][j].
// Carry (mean, cov) lives in shared memory across the T=200 sequential steps.
__global__ __launch_bounds__(256, 1)
void kalman_kernel(const float* __restrict__ y,      // [G,T,M]
                   const float* __restrict__ F,      // [G,T,S,S]
                   const float* __restrict__ H,      // [G,T,M,S]
                   const float* __restrict__ Q,      // [G,T,S,S]
                   const float* __restrict__ R,      // [G,T,M,M]
                   const float* __restrict__ init_mean, // [G,S]
                   const float* __restrict__ init_cov,  // [G,S,S]
                   float* __restrict__ out_means,    // [G,T,S]
                   float* __restrict__ out_covs)     // [G,T,S,S]
{
    const int g   = blockIdx.x;
    const int tid = threadIdx.x;
    const int i   = tid >> 4;   // 0..15
    const int j   = tid & 15;   // 0..15

    __shared__ float sMean[Sn];
    __shared__ float sMeanU[Sn];
    __shared__ float sCov[Sn][Sn + 1];    // +1 pad: conflict-free column access
    __shared__ float sF[Sn][Sn + 1];
    __shared__ float sQ[Sn][Sn + 1];
    __shared__ float sCovU[Sn][Sn + 1];
    __shared__ float sT1[Sn][Sn + 1];
    __shared__ float sH[Mn][Sn];
    __shared__ float sHP[Mn][Sn];
    __shared__ float sR[Mn][Mn];
    __shared__ float sSsig[Mn][Mn];
    __shared__ float sSinv[Mn][Mn];
    __shared__ float sK[Sn][Mn];
    __shared__ float sY[Mn];
    __shared__ float sResid[Mn];

    // ---- init carry ----
    if (tid < Sn) sMean[tid] = init_mean[(size_t)g * Sn + tid];
    sCov[i][j] = init_cov[(size_t)g * Sn * Sn + tid];

    const float* yG = y + (size_t)g * Tn * Mn;
    const float* FG = F + (size_t)g * Tn * Sn * Sn;
    const float* HG = H + (size_t)g * Tn * Mn * Sn;
    const float* QG = Q + (size_t)g * Tn * Sn * Sn;
    const float* RG = R + (size_t)g * Tn * Mn * Mn;
    float* mOut = out_means + (size_t)g * Tn * Sn;
    float* cOut = out_covs  + (size_t)g * Tn * Sn * Sn;

    // ---- prefetch t=0 inputs into registers ----
    float rF = FG[tid];
    float rQ = QG[tid];
    float rH = (tid < Mn * Sn) ? HG[tid] : 0.0f;
    float rR = (tid < Mn * Mn) ? RG[tid] : 0.0f;
    float rY = (tid < Mn)      ? yG[tid] : 0.0f;

    for (int t = 0; t < Tn; ++t) {
        // ---- emit 1-step-ahead prediction (the carry) for time t ----
        // (own element, written by this thread last iter: no sync needed)
        if (tid < Sn) mOut[t * Sn + tid] = sMean[tid];
        cOut[t * Sn * Sn + tid] = sCov[i][j];

        // ---- stage prefetched inputs to smem ----
        sF[i][j] = rF;
        sQ[i][j] = rQ;
        if (tid < Mn * Sn) sH[tid >> 4][tid & 15] = rH;
        if (tid < Mn * Mn) sR[tid >> 2][tid & 3]  = rR;
        if (tid < Mn)      sY[tid] = rY;
        __syncthreads();

        // ---- prefetch t+1 (overlaps with all the compute below) ----
        if (t + 1 < Tn) {
            const int o = (t + 1);
            rF = FG[o * Sn * Sn + tid];
            rQ = QG[o * Sn * Sn + tid];
            if (tid < Mn * Sn) rH = HG[o * Mn * Sn + tid];
            if (tid < Mn * Mn) rR = RG[o * Mn * Mn + tid];
            if (tid < Mn)      rY = yG[o * Mn + tid];
        }

        // ---- HP = H @ P  [4,16], resid = y - H@mean [4] ----
        if (tid < Mn * Sn) {
            const int m = tid >> 4, s = tid & 15;
            float acc = 0.0f;
            #pragma unroll
            for (int n = 0; n < Sn; ++n) acc += sH[m][n] * sCov[n][s];
            sHP[m][s] = acc;
        }
        if (tid < Mn) {
            float acc = sY[tid];
            #pragma unroll
            for (int n = 0; n < Sn; ++n) acc -= sH[tid][n] * sMean[n];
            sResid[tid] = acc;
        }
        __syncthreads();

        // ---- Ssig = HP @ H' + R  [4,4] ----
        if (tid < Mn * Mn) {
            const int m = tid >> 2, k = tid & 3;
            float acc = sR[m][k];
            #pragma unroll
            for (int n = 0; n < Sn; ++n) acc += sHP[m][n] * sH[k][n];
            sSsig[m][k] = acc;
        }
        __syncthreads();

        // ---- Sinv = Ssig^{-1} (closed-form 4x4 adjugate; SPD, well-conditioned) ----
        if (tid == 0) {
            const float m00 = sSsig[0][0], m01 = sSsig[0][1], m02 = sSsig[0][2], m03 = sSsig[0][3];
            const float m10 = sSsig[1][0], m11 = sSsig[1][1], m12 = sSsig[1][2], m13 = sSsig[1][3];
            const float m20 = sSsig[2][0], m21 = sSsig[2][1], m22 = sSsig[2][2], m23 = sSsig[2][3];
            const float m30 = sSsig[3][0], m31 = sSsig[3][1], m32 = sSsig[3][2], m33 = sSsig[3][3];

            const float A2323 = m22*m33 - m23*m32;
            const float A1323 = m21*m33 - m23*m31;
            const float A1223 = m21*m32 - m22*m31;
            const float A0323 = m20*m33 - m23*m30;
            const float A0223 = m20*m32 - m22*m30;
            const float A0123 = m20*m31 - m21*m30;
            const float A2313 = m12*m33 - m13*m32;
            const float A1313 = m11*m33 - m13*m31;
            const float A1213 = m11*m32 - m12*m31;
            const float A2312 = m12*m23 - m13*m22;
            const float A1312 = m11*m23 - m13*m21;
            const float A1212 = m11*m22 - m12*m21;
            const float A0313 = m10*m33 - m13*m30;
            const float A0213 = m10*m32 - m12*m30;
            const float A0312 = m10*m23 - m13*m20;
            const float A0212 = m10*m22 - m12*m20;
            const float A0113 = m10*m31 - m11*m30;
            const float A0112 = m10*m21 - m11*m20;

            float det = m00 * (m11*A2323 - m12*A1323 + m13*A1223)
                      - m01 * (m10*A2323 - m12*A0323 + m13*A0223)
                      + m02 * (m10*A1323 - m11*A0323 + m13*A0123)
                      - m03 * (m10*A1223 - m11*A0223 + m12*A0123);
            const float inv = 1.0f / det;

            sSinv[0][0] =  (m11*A2323 - m12*A1323 + m13*A1223) * inv;
            sSinv[0][1] = -(m01*A2323 - m02*A1323 + m03*A1223) * inv;
            sSinv[0][2] =  (m01*A2313 - m02*A1313 + m03*A1213) * inv;
            sSinv[0][3] = -(m01*A2312 - m02*A1312 + m03*A1212) * inv;
            sSinv[1][0] = -(m10*A2323 - m12*A0323 + m13*A0223) * inv;
            sSinv[1][1] =  (m00*A2323 - m02*A0323 + m03*A0223) * inv;
            sSinv[1][2] = -(m00*A2313 - m02*A0313 + m03*A0213) * inv;
            sSinv[1][3] =  (m00*A2312 - m02*A0312 + m03*A0212) * inv;
            sSinv[2][0] =  (m10*A1323 - m11*A0323 + m13*A0123) * inv;
            sSinv[2][1] = -(m00*A1323 - m01*A0323 + m03*A0123) * inv;
            sSinv[2][2] =  (m00*A1313 - m01*A0313 + m03*A0113) * inv;
            sSinv[2][3] = -(m00*A1312 - m01*A0312 + m03*A0112) * inv;
            sSinv[3][0] = -(m10*A1223 - m11*A0223 + m12*A0123) * inv;
            sSinv[3][1] =  (m00*A1223 - m01*A0223 + m02*A0123) * inv;
            sSinv[3][2] = -(m00*A1213 - m01*A0213 + m02*A0113) * inv;
            sSinv[3][3] =  (m00*A1212 - m01*A0212 + m02*A0112) * inv;
        }
        __syncthreads();

        // ---- K = (Sinv @ HP)^T  [16,4]:  K[s][m] = sum_k Sinv[m][k] * HP[k][s] ----
        if (tid < Sn * Mn) {
            const int s = tid >> 2, m = tid & 3;
            float acc = 0.0f;
            #pragma unroll
            for (int k = 0; k < Mn; ++k) acc += sSinv[m][k] * sHP[k][s];
            sK[s][m] = acc;
        }
        __syncthreads();

        // ---- mean_u = mean + K@resid; cov_u = P - K @ (H P) ----
        if (tid < Sn) {
            float acc = sMean[tid];
            #pragma unroll
            for (int m = 0; m < Mn; ++m) acc += sK[tid][m] * sResid[m];
            sMeanU[tid] = acc;
        }
        {
            float acc = sCov[i][j];
            #pragma unroll
            for (int m = 0; m < Mn; ++m) acc -= sK[i][m] * sHP[m][j];
            sCovU[i][j] = acc;
        }
        __syncthreads();

        // ---- predict: T1 = F @ cov_u; mean = F @ mean_u ----
        {
            float acc = 0.0f;
            #pragma unroll
            for (int k = 0; k < Sn; ++k) acc += sF[i][k] * sCovU[k][j];
            sT1[i][j] = acc;
        }
        if (tid < Sn) {
            float acc = 0.0f;
            #pragma unroll
            for (int k = 0; k < Sn; ++k) acc += sF[tid][k] * sMeanU[k];
            sMean[tid] = acc;  // safe: last read of sMean was before previous sync
        }
        __syncthreads();

        // ---- cov = T1 @ F' + Q ----
        {
            float acc = sQ[i][j];
            #pragma unroll
            for (int k = 0; k < Sn; ++k) acc += sT1[i][k] * sF[j][k];
            sCov[i][j] = acc;  // own element; next cross-thread read is after next sync
        }
        // loop top's load-stage __syncthreads() protects the sCov update
        __syncthreads();
    }
}

extern "C" void kernel_launch(void* const* d_in, const int* in_sizes, int n_in,
                              void* d_out, int out_size) {
    const float* y  = (const float*)d_in[0];   // [G,T,M]
    const float* F  = (const float*)d_in[1];   // [G,T,S,S]
    const float* H  = (const float*)d_in[2];   // [G,T,M,S]
    const float* Q  = (const float*)d_in[3];   // [G,T,S,S]
    const float* R  = (const float*)d_in[4];   // [G,T,M,M]
    const float* im = (const float*)d_in[5];   // [G,S]
    const float* ic = (const float*)d_in[6];   // [G,S,S]

    float* out       = (float*)d_out;
    float* out_means = out;                                         // G*T*S
    float* out_covs  = out_means + (size_t)Gn * Tn * Sn;            // G*T*S*S
    float* out_R     = out_covs  + (size_t)Gn * Tn * Sn * Sn;       // G*T*M*M
    float* out_H     = out_R     + (size_t)Gn * Tn * Mn * Mn;       // G*T*M*S

    // R and H are passthrough outputs: straight D2D copies (graph-capturable)
    cudaMemcpyAsync(out_R, R, sizeof(float) * (size_t)Gn * Tn * Mn * Mn,
                    cudaMemcpyDeviceToDevice, 0);
    cudaMemcpyAsync(out_H, H, sizeof(float) * (size_t)Gn * Tn * Mn * Sn,
                    cudaMemcpyDeviceToDevice, 0);

    kalman_kernel<<<Gn, 256>>>(y, F, H, Q, R, im, ic, out_means, out_covs);
}

// round 2
// speedup vs baseline: 2.5914x; 2.5914x over previous
#include <cuda_runtime.h>

#define Gn 1024
#define Tn 200
#define Sn 16
#define Mn 4
#define SW 20                 // padded row stride (floats); 80B rows keep float4 alignment
#define WARPS_PER_CTA 2
#define PER_WARP_SMEM 1296    // floats; 5184B, 16B-multiple

// One WARP per group. Lane l owns cov row i=l>>1, columns jb=(l&1)*8 .. +7.
// Carry (mean, cov) lives in registers; cross-lane operands staged via smem
// with warp-level syncs only. No __syncthreads anywhere.
__global__ __launch_bounds__(WARPS_PER_CTA * 32)
void kalman_kernel(const float* __restrict__ y,        // [G,T,M]
                   const float* __restrict__ F,        // [G,T,S,S]
                   const float* __restrict__ H,        // [G,T,M,S]
                   const float* __restrict__ Q,        // [G,T,S,S]
                   const float* __restrict__ R,        // [G,T,M,M]
                   const float* __restrict__ init_mean,// [G,S]
                   const float* __restrict__ init_cov, // [G,S,S]
                   float* __restrict__ out_means,      // [G,T,S]
                   float* __restrict__ out_covs)       // [G,T,S,S]
{
    __shared__ float smemAll[WARPS_PER_CTA * PER_WARP_SMEM];
    const int w    = threadIdx.x >> 5;
    const int lane = threadIdx.x & 31;
    const int g    = blockIdx.x * WARPS_PER_CTA + w;

    float* base   = smemAll + w * PER_WARP_SMEM;
    float* sP     = base;           // [16][SW] covariance carry / cov_u (in place)
    float* sF     = base + 320;     // [16][SW]
    float* sFt    = base + 640;     // [16][SW]  sFt[k][j] = F[j][k]
    float* sHP    = base + 960;     // [4][SW]
    float* sH     = base + 1040;    // [4][SW]
    float* sK     = base + 1120;    // [16][4]
    float* sSinv  = base + 1184;    // [4][4]
    float* sMean  = base + 1200;    // [16]
    float* sMeanU = base + 1216;    // [16]
    float* sR     = base + 1232;    // [16]
    float* sy     = base + 1248;    // [4]
    float* sResid = base + 1252;    // [4]
    float* sSsig  = base + 1256;    // [16]

    const int i  = lane >> 1;
    const int jb = (lane & 1) * 8;

    const float* yG = y + (size_t)g * Tn * Mn;
    const float* FG = F + (size_t)g * Tn * Sn * Sn;
    const float* HG = H + (size_t)g * Tn * Mn * Sn;
    const float* QG = Q + (size_t)g * Tn * Sn * Sn;
    const float* RG = R + (size_t)g * Tn * Mn * Mn;
    float* mOut = out_means + (size_t)g * Tn * Sn;
    float* cOut = out_covs  + (size_t)g * Tn * Sn * Sn;

    // ---- carry in registers ----
    float cCov[8];
    {
        const float4* p = (const float4*)(init_cov + (size_t)g * Sn * Sn + i * Sn + jb);
        float4 a = p[0], b = p[1];
        cCov[0]=a.x; cCov[1]=a.y; cCov[2]=a.z; cCov[3]=a.w;
        cCov[4]=b.x; cCov[5]=b.y; cCov[6]=b.z; cCov[7]=b.w;
    }
    float cMean = (lane < Sn) ? init_mean[(size_t)g * Sn + lane] : 0.0f;

    // ---- prefetch t=0 inputs ----
    float pF[8], pQ[8], pH0, pH1, pR_, pY_;
    {
        const float4* f4 = (const float4*)(FG + lane * 8);
        float4 a = f4[0], b = f4[1];
        pF[0]=a.x; pF[1]=a.y; pF[2]=a.z; pF[3]=a.w; pF[4]=b.x; pF[5]=b.y; pF[6]=b.z; pF[7]=b.w;
        const float4* q4 = (const float4*)(QG + lane * 8);
        a = q4[0]; b = q4[1];
        pQ[0]=a.x; pQ[1]=a.y; pQ[2]=a.z; pQ[3]=a.w; pQ[4]=b.x; pQ[5]=b.y; pQ[6]=b.z; pQ[7]=b.w;
        float2 h2 = *(const float2*)(HG + lane * 2);
        pH0 = h2.x; pH1 = h2.y;
        pR_ = (lane < 16) ? RG[lane] : 0.0f;
        pY_ = (lane < 4)  ? yG[lane] : 0.0f;
    }

    for (int t = 0; t < Tn; ++t) {
        // ---- emit 1-step-ahead prediction for time t (from registers) ----
        {
            float4* o = (float4*)(cOut + (size_t)t * 256 + i * 16 + jb);
            o[0] = make_float4(cCov[0], cCov[1], cCov[2], cCov[3]);
            o[1] = make_float4(cCov[4], cCov[5], cCov[6], cCov[7]);
            if (lane < Sn) mOut[t * Sn + lane] = cMean;
        }

        // ---- stage inputs + carry into smem ----
        float qCur[8];
        #pragma unroll
        for (int r = 0; r < 8; ++r) qCur[r] = pQ[r];
        {
            float4* p4 = (float4*)(sP + i * SW + jb);
            p4[0] = make_float4(cCov[0], cCov[1], cCov[2], cCov[3]);
            p4[1] = make_float4(cCov[4], cCov[5], cCov[6], cCov[7]);
            float4* f4 = (float4*)(sF + i * SW + jb);
            f4[0] = make_float4(pF[0], pF[1], pF[2], pF[3]);
            f4[1] = make_float4(pF[4], pF[5], pF[6], pF[7]);
            #pragma unroll
            for (int r = 0; r < 8; ++r) sFt[(jb + r) * SW + i] = pF[r];
            const int hi = lane * 2;
            sH[(hi >> 4) * SW + (hi & 15)]     = pH0;
            sH[(hi >> 4) * SW + (hi & 15) + 1] = pH1;
            if (lane < 16) { sR[lane] = pR_; sMean[lane] = cMean; }
            if (lane < 4)  sy[lane] = pY_;
        }
        __syncwarp();

        // ---- prefetch t+1 (overlaps with compute) ----
        if (t + 1 < Tn) {
            const float4* f4 = (const float4*)(FG + (size_t)(t + 1) * 256 + lane * 8);
            float4 a = f4[0], b = f4[1];
            pF[0]=a.x; pF[1]=a.y; pF[2]=a.z; pF[3]=a.w; pF[4]=b.x; pF[5]=b.y; pF[6]=b.z; pF[7]=b.w;
            const float4* q4 = (const float4*)(QG + (size_t)(t + 1) * 256 + lane * 8);
            a = q4[0]; b = q4[1];
            pQ[0]=a.x; pQ[1]=a.y; pQ[2]=a.z; pQ[3]=a.w; pQ[4]=b.x; pQ[5]=b.y; pQ[6]=b.z; pQ[7]=b.w;
            float2 h2 = *(const float2*)(HG + (size_t)(t + 1) * 64 + lane * 2);
            pH0 = h2.x; pH1 = h2.y;
            if (lane < 16) pR_ = RG[(size_t)(t + 1) * 16 + lane];
            if (lane < 4)  pY_ = yG[(size_t)(t + 1) * 4 + lane];
        }

        // ---- Phase 1: HP = H @ P (all 32 lanes: 2 outputs each), resid, F row -> regs ----
        {
            const int m = lane >> 3, sp = (lane & 7) * 2;
            float a0 = 0.0f, a1 = 0.0f;
            #pragma unroll
            for (int n = 0; n < 16; ++n) {
                const float h = sH[m * SW + n];
                const float2 p = *(const float2*)(sP + n * SW + sp);
                a0 += h * p.x; a1 += h * p.y;
            }
            sHP[m * SW + sp]     = a0;
            sHP[m * SW + sp + 1] = a1;
        }
        if (lane < 4) {
            float rr = sy[lane];
            #pragma unroll
            for (int n = 0; n < 16; ++n) rr -= sH[lane * SW + n] * sMean[n];
            sResid[lane] = rr;
        }
        float fr[16];
        {
            const float4* f4 = (const float4*)(sF + i * SW);
            float4 a = f4[0], b = f4[1], c = f4[2], d = f4[3];
            fr[0]=a.x; fr[1]=a.y; fr[2]=a.z; fr[3]=a.w;
            fr[4]=b.x; fr[5]=b.y; fr[6]=b.z; fr[7]=b.w;
            fr[8]=c.x; fr[9]=c.y; fr[10]=c.z; fr[11]=c.w;
            fr[12]=d.x; fr[13]=d.y; fr[14]=d.z; fr[15]=d.w;
        }
        __syncwarp();

        // ---- Phase 2: Ssig = HP @ H' + R (lanes 0..15) ----
        if (lane < 16) {
            const int m = lane >> 2, k = lane & 3;
            float a = sR[lane];
            #pragma unroll
            for (int n = 0; n < 16; ++n) a += sHP[m * SW + n] * sH[k * SW + n];
            sSsig[lane] = a;
        }
        __syncwarp();

        // ---- Phase 3: 4x4 inverse via cofactors, one per lane (0..15) ----
        if (lane < 16) {
            const int ii = lane >> 2, jj = lane & 3;
            const int r0 = (ii == 0) ? 1 : 0;
            const int r1 = (ii <= 1) ? 2 : 1;
            const int r2 = (ii <= 2) ? 3 : 2;
            const int c0 = (jj == 0) ? 1 : 0;
            const int c1 = (jj <= 1) ? 2 : 1;
            const int c2 = (jj <= 2) ? 3 : 2;
            #define MM(a, b) sSsig[(a) * 4 + (b)]
            float d3 = MM(r0, c0) * (MM(r1, c1) * MM(r2, c2) - MM(r1, c2) * MM(r2, c1))
                     - MM(r0, c1) * (MM(r1, c0) * MM(r2, c2) - MM(r1, c2) * MM(r2, c0))
                     + MM(r0, c2) * (MM(r1, c0) * MM(r2, c1) - MM(r1, c1) * MM(r2, c0));
            #undef MM
            float cof = ((ii + jj) & 1) ? -d3 : d3;
            // det = sum_j Ssig[0][j] * Cof[0][j]; reduce among lanes 0..3, broadcast
            float part = (ii == 0) ? sSsig[jj] * cof : 0.0f;
            part += __shfl_xor_sync(0xffffu, part, 1);
            part += __shfl_xor_sync(0xffffu, part, 2);
            const float det = __shfl_sync(0xffffu, part, 0);
            sSinv[jj * 4 + ii] = cof * (1.0f / det);   // inv = adj^T / det
        }
        __syncwarp();

        // ---- Phase 4: K[s][m] = sum_k Sinv[m][k] * HP[k][s] (2 outputs/lane) ----
        {
            const int s = lane >> 1, mb = (lane & 1) * 2;
            float a0 = 0.0f, a1 = 0.0f;
            #pragma unroll
            for (int k = 0; k < 4; ++k) {
                const float hp = sHP[k * SW + s];
                a0 += sSinv[mb * 4 + k] * hp;
                a1 += sSinv[(mb + 1) * 4 + k] * hp;
            }
            sK[s * 4 + mb]     = a0;
            sK[s * 4 + mb + 1] = a1;
        }
        __syncwarp();

        // ---- Phase 5: mean_u; cov_u = P - K @ HP (own row, in place into sP) ----
        if (lane < 16) {
            float a = sMean[lane];
            #pragma unroll
            for (int m = 0; m < 4; ++m) a += sK[lane * 4 + m] * sResid[m];
            sMeanU[lane] = a;
        }
        {
            const float4 k4 = *(const float4*)(sK + i * 4);
            const float kk[4] = {k4.x, k4.y, k4.z, k4.w};
            float cu[8];
            #pragma unroll
            for (int r = 0; r < 8; ++r) cu[r] = cCov[r];
            #pragma unroll
            for (int m = 0; m < 4; ++m) {
                const float4 b0 = *(const float4*)(sHP + m * SW + jb);
                const float4 b1 = *(const float4*)(sHP + m * SW + jb + 4);
                cu[0] -= kk[m] * b0.x; cu[1] -= kk[m] * b0.y;
                cu[2] -= kk[m] * b0.z; cu[3] -= kk[m] * b0.w;
                cu[4] -= kk[m] * b1.x; cu[5] -= kk[m] * b1.y;
                cu[6] -= kk[m] * b1.z; cu[7] -= kk[m] * b1.w;
            }
            float4* p4 = (float4*)(sP + i * SW + jb);
            p4[0] = make_float4(cu[0], cu[1], cu[2], cu[3]);
            p4[1] = make_float4(cu[4], cu[5], cu[6], cu[7]);
        }
        __syncwarp();

        // ---- Phase 6: T1 = F @ cov_u (row segment in regs); mean = F @ mean_u ----
        float t1[8];
        #pragma unroll
        for (int r = 0; r < 8; ++r) t1[r] = 0.0f;
        #pragma unroll
        for (int k = 0; k < 16; ++k) {
            const float4 b0 = *(const float4*)(sP + k * SW + jb);
            const float4 b1 = *(const float4*)(sP + k * SW + jb + 4);
            const float fk = fr[k];
            t1[0] += fk * b0.x; t1[1] += fk * b0.y; t1[2] += fk * b0.z; t1[3] += fk * b0.w;
            t1[4] += fk * b1.x; t1[5] += fk * b1.y; t1[6] += fk * b1.z; t1[7] += fk * b1.w;
        }
        if (lane < 16) {
            float a = 0.0f;
            #pragma unroll
            for (int k = 0; k < 16; ++k) a += sF[lane * SW + k] * sMeanU[k];
            cMean = a;
        }
        __syncwarp();

        // ---- Phase 7: cov = T1 @ F' + Q  (gather partner T1 half via shfl) ----
        float t1f[16];
        #pragma unroll
        for (int r = 0; r < 8; ++r) {
            const float o = __shfl_xor_sync(0xffffffffu, t1[r], 1);
            if ((lane & 1) == 0) { t1f[r] = t1[r]; t1f[8 + r] = o; }
            else                 { t1f[r] = o;     t1f[8 + r] = t1[r]; }
        }
        #pragma unroll
        for (int r = 0; r < 8; ++r) cCov[r] = qCur[r];
        #pragma unroll
        for (int k = 0; k < 16; ++k) {
            const float4 b0 = *(const float4*)(sFt + k * SW + jb);
            const float4 b1 = *(const float4*)(sFt + k * SW + jb + 4);
            const float tk = t1f[k];
            cCov[0] += tk * b0.x; cCov[1] += tk * b0.y; cCov[2] += tk * b0.z; cCov[3] += tk * b0.w;
            cCov[4] += tk * b1.x; cCov[5] += tk * b1.y; cCov[6] += tk * b1.z; cCov[7] += tk * b1.w;
        }
        __syncwarp();   // protect staged smem from next-iter overwrite
    }
}

extern "C" void kernel_launch(void* const* d_in, const int* in_sizes, int n_in,
                              void* d_out, int out_size) {
    const float* y  = (const float*)d_in[0];   // [G,T,M]
    const float* F  = (const float*)d_in[1];   // [G,T,S,S]
    const float* H  = (const float*)d_in[2];   // [G,T,M,S]
    const float* Q  = (const float*)d_in[3];   // [G,T,S,S]
    const float* R  = (const float*)d_in[4];   // [G,T,M,M]
    const float* im = (const float*)d_in[5];   // [G,S]
    const float* ic = (const float*)d_in[6];   // [G,S,S]

    float* out       = (float*)d_out;
    float* out_means = out;                                    // G*T*S
    float* out_covs  = out_means + (size_t)Gn * Tn * Sn;       // G*T*S*S
    float* out_R     = out_covs  + (size_t)Gn * Tn * Sn * Sn;  // G*T*M*M
    float* out_H     = out_R     + (size_t)Gn * Tn * Mn * Mn;  // G*T*M*S

    cudaMemcpyAsync(out_R, R, sizeof(float) * (size_t)Gn * Tn * Mn * Mn,
                    cudaMemcpyDeviceToDevice, 0);
    cudaMemcpyAsync(out_H, H, sizeof(float) * (size_t)Gn * Tn * Mn * Sn,
                    cudaMemcpyDeviceToDevice, 0);

    kalman_kernel<<<Gn / WARPS_PER_CTA, WARPS_PER_CTA * 32>>>(
        y, F, H, Q, R, im, ic, out_means, out_covs);
}